// round 4
// baseline (speedup 1.0000x reference)
#include <cuda_runtime.h>
#include <cstdint>

#define N_NODES 2048
#define F_FEAT  64
#define H_HID   64
#define C_OUT   8

// g transposed: [c][j], bias included (written by g_kernel, read by main_kernel)
__device__ float g_gT[C_OUT * N_NODES];

// ---------------------------------------------------------------------------
// g kernel: g[j,c] = sum_f sum_h relu(x[j,f]*W1[f,h]+b1[f,h]) * W2[f,h,c]
//                    + sum_f b2[f,c]
// 128 blocks x 128 threads; each warp handles 4 rows so W1/b1/W2 loads are
// amortized 4x (pushes kernel from L1-BW-bound to FFMA-bound).
// ---------------------------------------------------------------------------
__global__ void __launch_bounds__(128) g_kernel(const float* __restrict__ x,
                                                const float* __restrict__ W1,
                                                const float* __restrict__ b1,
                                                const float* __restrict__ W2,
                                                const float* __restrict__ b2) {
    __shared__ float s_bias[64 * C_OUT];

    int tid  = threadIdx.x;
    int lane = tid & 31;
    int warp = tid >> 5;

    // block-shared bias[c] = sum_f b2[f,c]
    if (tid < 64) {
        float4 v0 = *(const float4*)(b2 + tid * 8);
        float4 v1 = *(const float4*)(b2 + tid * 8 + 4);
        s_bias[tid * 8 + 0] = v0.x; s_bias[tid * 8 + 1] = v0.y;
        s_bias[tid * 8 + 2] = v0.z; s_bias[tid * 8 + 3] = v0.w;
        s_bias[tid * 8 + 4] = v1.x; s_bias[tid * 8 + 5] = v1.y;
        s_bias[tid * 8 + 6] = v1.z; s_bias[tid * 8 + 7] = v1.w;
    }
    __syncthreads();
#pragma unroll
    for (int off = 32; off >= 1; off >>= 1) {
        if (tid < off)
#pragma unroll
            for (int c = 0; c < C_OUT; c++)
                s_bias[tid * 8 + c] += s_bias[(tid + off) * 8 + c];
        __syncthreads();
    }

    int r0 = blockIdx.x * 16 + warp * 4;  // 4 consecutive rows per warp
    int h0 = lane, h1 = lane + 32;

    // preload x rows; broadcast per-f via shfl
    float xr[4][2];
#pragma unroll
    for (int r = 0; r < 4; r++) {
        xr[r][0] = x[(r0 + r) * F_FEAT + lane];
        xr[r][1] = x[(r0 + r) * F_FEAT + lane + 32];
    }

    float acc[4][C_OUT];
#pragma unroll
    for (int r = 0; r < 4; r++)
#pragma unroll
        for (int c = 0; c < C_OUT; c++) acc[r][c] = 0.f;

#pragma unroll 8
    for (int f = 0; f < F_FEAT; f++) {
        float w1a = W1[f * 64 + h0], w1b = W1[f * 64 + h1];
        float b1a = b1[f * 64 + h0], b1b = b1[f * 64 + h1];
        const float4* wa = (const float4*)(W2 + (size_t)(f * 64 + h0) * 8);
        const float4* wb = (const float4*)(W2 + (size_t)(f * 64 + h1) * 8);
        float4 a0 = wa[0], a1 = wa[1];
        float4 b0v = wb[0], b1v = wb[1];

#pragma unroll
        for (int r = 0; r < 4; r++) {
            float xsrc = (f < 32) ? xr[r][0] : xr[r][1];
            float xv = __shfl_sync(0xffffffffu, xsrc, f & 31);
            float ha = fmaxf(fmaf(xv, w1a, b1a), 0.f);
            float hb = fmaxf(fmaf(xv, w1b, b1b), 0.f);

            acc[r][0] = fmaf(ha, a0.x, fmaf(hb, b0v.x, acc[r][0]));
            acc[r][1] = fmaf(ha, a0.y, fmaf(hb, b0v.y, acc[r][1]));
            acc[r][2] = fmaf(ha, a0.z, fmaf(hb, b0v.z, acc[r][2]));
            acc[r][3] = fmaf(ha, a0.w, fmaf(hb, b0v.w, acc[r][3]));
            acc[r][4] = fmaf(ha, a1.x, fmaf(hb, b1v.x, acc[r][4]));
            acc[r][5] = fmaf(ha, a1.y, fmaf(hb, b1v.y, acc[r][5]));
            acc[r][6] = fmaf(ha, a1.z, fmaf(hb, b1v.z, acc[r][6]));
            acc[r][7] = fmaf(ha, a1.w, fmaf(hb, b1v.w, acc[r][7]));
        }
    }

#pragma unroll
    for (int r = 0; r < 4; r++)
#pragma unroll
        for (int c = 0; c < C_OUT; c++)
#pragma unroll
            for (int o = 16; o; o >>= 1)
                acc[r][c] += __shfl_xor_sync(0xffffffffu, acc[r][c], o);

    if (lane == 0) {
#pragma unroll
        for (int r = 0; r < 4; r++)
#pragma unroll
            for (int c = 0; c < C_OUT; c++)
                g_gT[c * N_NODES + r0 + r] = acc[r][c] + s_bias[c];
    }
}

// ---------------------------------------------------------------------------
// Main kernel: out[i,c] = sum_j m(nd[i,j]/nm[i,j]) * g[j,c]
//
// m(d) = sum_h Wm2[h]*relu(Wm1[h]*d+bm1[h]) + bm2 is piecewise-linear with
// 64 breakpoints. Each block rebuilds the sorted breakpoint + prefix
// coefficient tables in shared (warp-shfl scan, ~500 cyc, no setup launch).
// Segment lookup uses a fast path (d above max breakpoint -> k=64, one
// broadcast LDS) with a 6-step binary-search fallback.
//
// 128 blocks (single wave) x 8 warps; 2 rows per warp so each gT LDS.128
// serves two accumulations. nd/nm streamed with __ldcs.
// ---------------------------------------------------------------------------
__global__ void __launch_bounds__(256) main_kernel(const float* __restrict__ nd,
                                                   const float* __restrict__ nm,
                                                   const float* __restrict__ Wm1,
                                                   const float* __restrict__ bm1,
                                                   const float* __restrict__ Wm2,
                                                   const float* __restrict__ bm2,
                                                   float* __restrict__ out) {
    extern __shared__ float sh[];
    float* gTs  = sh;                        // [8][2048]
    float* bps  = gTs + C_OUT * N_NODES;     // [64] sorted breakpoints
    float* As   = bps + 64;                  // [65]
    float* Bs   = As + 65;                   // [65]
    float* w_t  = Bs + 65;                   // [64] scratch
    float* w_bA = w_t + 64;                  // [64]
    float* w_bB = w_bA + 64;                 // [64]
    float* s_dA = w_bB + 64;                 // [64] sorted deltas
    float* s_dB = s_dA + 64;                 // [64]

    int tid = threadIdx.x;

    // stage gT (64KB) while computing the PWL table
    for (int i = tid; i < C_OUT * N_NODES; i += 256)
        gTs[i] = g_gT[i];

    float da = 0.f, db = 0.f;
    float t_local = 0.f;
    if (tid < 64) {
        float a = Wm1[tid], b = bm1[tid], c = Wm2[tid];
        float t, bA = 0.f, bB = 0.f;
        if (a != 0.f) {
            t = -b / a;
            float pa = a * c, pb = b * c;
            if (a > 0.f) { da = pa;  db = pb; }
            else         { da = -pa; db = -pb; bA = pa; bB = pb; }
        } else {
            t = __int_as_float(0x7f800000);   // +inf: never crossed
            if (b > 0.f) bB = b * c;
        }
        w_t[tid] = t; w_bA[tid] = bA; w_bB[tid] = bB;
        t_local = t;
    }
    __syncthreads();

    if (tid < 64) {
        int rank = 0;
        for (int h2 = 0; h2 < 64; h2++) {
            float o = w_t[h2];
            rank += (o < t_local) || (o == t_local && h2 < tid);
        }
        bps[rank] = t_local; s_dA[rank] = da; s_dB[rank] = db;
    }
    __syncthreads();

    // warp 0: base-state reduce + inclusive scan of deltas (2 elems/lane)
    if (tid < 32) {
        float a0 = s_dA[2 * tid], a1 = s_dA[2 * tid + 1];
        float b0 = s_dB[2 * tid], b1 = s_dB[2 * tid + 1];
        float ra = w_bA[2 * tid] + w_bA[2 * tid + 1];
        float rb = w_bB[2 * tid] + w_bB[2 * tid + 1];
#pragma unroll
        for (int o = 16; o; o >>= 1) {
            ra += __shfl_xor_sync(0xffffffffu, ra, o);
            rb += __shfl_xor_sync(0xffffffffu, rb, o);
        }
        float A0 = ra, B0 = rb + bm2[0];

        float sa = a0 + a1, sb = b0 + b1;
        float ia = sa, ib = sb;
#pragma unroll
        for (int o = 1; o < 32; o <<= 1) {
            float ua = __shfl_up_sync(0xffffffffu, ia, o);
            float ub = __shfl_up_sync(0xffffffffu, ib, o);
            if (tid >= o) { ia += ua; ib += ub; }
        }
        float ea = ia - sa, eb = ib - sb;  // exclusive prefix
        if (tid == 0) { As[0] = A0; Bs[0] = B0; }
        As[2 * tid + 1] = A0 + ea + a0;
        Bs[2 * tid + 1] = B0 + eb + b0;
        As[2 * tid + 2] = A0 + ea + a0 + a1;
        Bs[2 * tid + 2] = B0 + eb + b0 + b1;
    }
    __syncthreads();

    int warp = tid >> 5, lane = tid & 31;
    int r0 = blockIdx.x * 16 + warp * 2;
    int r1 = r0 + 1;

    const float* d0 = nd + (size_t)r0 * N_NODES;
    const float* n0 = nm + (size_t)r0 * N_NODES;
    const float* d1 = nd + (size_t)r1 * N_NODES;
    const float* n1 = nm + (size_t)r1 * N_NODES;

    float top = bps[63];

    float acc0[C_OUT], acc1[C_OUT];
#pragma unroll
    for (int c = 0; c < C_OUT; c++) { acc0[c] = 0.f; acc1[c] = 0.f; }

#pragma unroll 2
    for (int jb = lane * 4; jb < N_NODES; jb += 128) {
        float4 dq0 = __ldcs((const float4*)(d0 + jb));
        float4 nq0 = __ldcs((const float4*)(n0 + jb));
        float4 dq1 = __ldcs((const float4*)(d1 + jb));
        float4 nq1 = __ldcs((const float4*)(n1 + jb));

        float dv0[4] = {dq0.x, dq0.y, dq0.z, dq0.w};
        float nv0[4] = {nq0.x, nq0.y, nq0.z, nq0.w};
        float dv1[4] = {dq1.x, dq1.y, dq1.z, dq1.w};
        float nv1[4] = {nq1.x, nq1.y, nq1.z, nq1.w};

        float m0[4], m1[4];
#pragma unroll
        for (int t = 0; t < 4; t++) {
            float d = __fdividef(dv0[t], nv0[t]);
            int k;
            if (top < d) k = 64;                      // fast path (uniform)
            else {
                k = 0;
#pragma unroll
                for (int s = 32; s >= 1; s >>= 1)
                    if (bps[k + s - 1] < d) k += s;
            }
            m0[t] = fmaf(As[k], d, Bs[k]);

            float e = __fdividef(dv1[t], nv1[t]);
            int k2;
            if (top < e) k2 = 64;
            else {
                k2 = 0;
#pragma unroll
                for (int s = 32; s >= 1; s >>= 1)
                    if (bps[k2 + s - 1] < e) k2 += s;
            }
            m1[t] = fmaf(As[k2], e, Bs[k2]);
        }

#pragma unroll
        for (int c = 0; c < C_OUT; c++) {
            float4 gv = *(const float4*)(gTs + c * N_NODES + jb);
            acc0[c] = fmaf(m0[0], gv.x, acc0[c]);
            acc0[c] = fmaf(m0[1], gv.y, acc0[c]);
            acc0[c] = fmaf(m0[2], gv.z, acc0[c]);
            acc0[c] = fmaf(m0[3], gv.w, acc0[c]);
            acc1[c] = fmaf(m1[0], gv.x, acc1[c]);
            acc1[c] = fmaf(m1[1], gv.y, acc1[c]);
            acc1[c] = fmaf(m1[2], gv.z, acc1[c]);
            acc1[c] = fmaf(m1[3], gv.w, acc1[c]);
        }
    }

#pragma unroll
    for (int c = 0; c < C_OUT; c++) {
#pragma unroll
        for (int o = 16; o; o >>= 1) {
            acc0[c] += __shfl_xor_sync(0xffffffffu, acc0[c], o);
            acc1[c] += __shfl_xor_sync(0xffffffffu, acc1[c], o);
        }
    }

    if (lane == 0) {
#pragma unroll
        for (int c = 0; c < C_OUT; c++) {
            out[r0 * C_OUT + c] = acc0[c];
            out[r1 * C_OUT + c] = acc1[c];
        }
    }
}

// ---------------------------------------------------------------------------
extern "C" void kernel_launch(void* const* d_in, const int* in_sizes, int n_in,
                              void* d_out, int out_size) {
    const float* x   = (const float*)d_in[0];
    const float* nd  = (const float*)d_in[1];
    const float* nm  = (const float*)d_in[2];
    const float* W1  = (const float*)d_in[3];
    const float* b1  = (const float*)d_in[4];
    const float* W2  = (const float*)d_in[5];
    const float* b2  = (const float*)d_in[6];
    const float* Wm1 = (const float*)d_in[7];
    const float* bm1 = (const float*)d_in[8];
    const float* Wm2 = (const float*)d_in[9];
    const float* bm2 = (const float*)d_in[10];
    float* out = (float*)d_out;

    size_t shmem = (size_t)(C_OUT * N_NODES + 64 + 65 + 65 + 5 * 64) * sizeof(float);
    cudaFuncSetAttribute(main_kernel, cudaFuncAttributeMaxDynamicSharedMemorySize,
                         (int)shmem);

    g_kernel<<<N_NODES / 16, 128>>>(x, W1, b1, W2, b2);
    main_kernel<<<N_NODES / 16, 256, shmem>>>(nd, nm, Wm1, bm1, Wm2, bm2, out);
}

// round 5
// speedup vs baseline: 1.2859x; 1.2859x over previous
#include <cuda_runtime.h>
#include <cstdint>

#define N_NODES 2048
#define F_FEAT  64
#define H_HID   64
#define C_OUT   8
#define JCHUNK  512
#define NSPLIT  (N_NODES / JCHUNK)   // 4

// g transposed: [c][j], bias included (written by g_kernel, read by main_kernel)
__device__ float g_gT[C_OUT * N_NODES];

// ---------------------------------------------------------------------------
// g kernel: g[j,c] = sum_f sum_h relu(x[j,f]*W1[f,h]+b1[f,h]) * W2[f,h,c]
//                    + sum_f b2[f,c]
// 128 blocks x 256 threads (8 warps); 2 rows per warp (weight loads amortized
// 2x -> L1 traffic below the FFMA floor). Also zeroes `out` for main_kernel's
// atomic accumulation.
// ---------------------------------------------------------------------------
__global__ void __launch_bounds__(256) g_kernel(const float* __restrict__ x,
                                                const float* __restrict__ W1,
                                                const float* __restrict__ b1,
                                                const float* __restrict__ W2,
                                                const float* __restrict__ b2,
                                                float* __restrict__ out) {
    __shared__ float s_bias[64 * C_OUT];

    int tid  = threadIdx.x;
    int lane = tid & 31;
    int warp = tid >> 5;

    // zero the output slice this block owns (out poisoned by harness)
    if (tid < 128)
        out[blockIdx.x * 128 + tid] = 0.f;

    // block-shared bias[c] = sum_f b2[f,c]
    if (tid < 64) {
        float4 v0 = *(const float4*)(b2 + tid * 8);
        float4 v1 = *(const float4*)(b2 + tid * 8 + 4);
        s_bias[tid * 8 + 0] = v0.x; s_bias[tid * 8 + 1] = v0.y;
        s_bias[tid * 8 + 2] = v0.z; s_bias[tid * 8 + 3] = v0.w;
        s_bias[tid * 8 + 4] = v1.x; s_bias[tid * 8 + 5] = v1.y;
        s_bias[tid * 8 + 6] = v1.z; s_bias[tid * 8 + 7] = v1.w;
    }
    __syncthreads();
#pragma unroll
    for (int off = 32; off >= 1; off >>= 1) {
        if (tid < off)
#pragma unroll
            for (int c = 0; c < C_OUT; c++)
                s_bias[tid * 8 + c] += s_bias[(tid + off) * 8 + c];
        __syncthreads();
    }

    int r0 = blockIdx.x * 16 + warp * 2;   // 2 rows per warp
    int h0 = lane, h1 = lane + 32;

    float xa0 = x[r0 * F_FEAT + lane];
    float xa1 = x[r0 * F_FEAT + lane + 32];
    float xb0 = x[(r0 + 1) * F_FEAT + lane];
    float xb1 = x[(r0 + 1) * F_FEAT + lane + 32];

    float acc0[C_OUT], acc1[C_OUT];
#pragma unroll
    for (int c = 0; c < C_OUT; c++) { acc0[c] = 0.f; acc1[c] = 0.f; }

#pragma unroll 4
    for (int f = 0; f < F_FEAT; f++) {
        float w1a = W1[f * 64 + h0], w1b = W1[f * 64 + h1];
        float bb1a = b1[f * 64 + h0], bb1b = b1[f * 64 + h1];
        const float4* wa = (const float4*)(W2 + (size_t)(f * 64 + h0) * 8);
        const float4* wb = (const float4*)(W2 + (size_t)(f * 64 + h1) * 8);
        float4 a0 = wa[0], a1 = wa[1];
        float4 b0v = wb[0], b1v = wb[1];

        float xv0 = __shfl_sync(0xffffffffu, (f < 32) ? xa0 : xa1, f & 31);
        float xv1 = __shfl_sync(0xffffffffu, (f < 32) ? xb0 : xb1, f & 31);

        float h0a = fmaxf(fmaf(xv0, w1a, bb1a), 0.f);
        float h0b = fmaxf(fmaf(xv0, w1b, bb1b), 0.f);
        float h1a = fmaxf(fmaf(xv1, w1a, bb1a), 0.f);
        float h1b = fmaxf(fmaf(xv1, w1b, bb1b), 0.f);

        acc0[0] = fmaf(h0a, a0.x, fmaf(h0b, b0v.x, acc0[0]));
        acc0[1] = fmaf(h0a, a0.y, fmaf(h0b, b0v.y, acc0[1]));
        acc0[2] = fmaf(h0a, a0.z, fmaf(h0b, b0v.z, acc0[2]));
        acc0[3] = fmaf(h0a, a0.w, fmaf(h0b, b0v.w, acc0[3]));
        acc0[4] = fmaf(h0a, a1.x, fmaf(h0b, b1v.x, acc0[4]));
        acc0[5] = fmaf(h0a, a1.y, fmaf(h0b, b1v.y, acc0[5]));
        acc0[6] = fmaf(h0a, a1.z, fmaf(h0b, b1v.z, acc0[6]));
        acc0[7] = fmaf(h0a, a1.w, fmaf(h0b, b1v.w, acc0[7]));

        acc1[0] = fmaf(h1a, a0.x, fmaf(h1b, b0v.x, acc1[0]));
        acc1[1] = fmaf(h1a, a0.y, fmaf(h1b, b0v.y, acc1[1]));
        acc1[2] = fmaf(h1a, a0.z, fmaf(h1b, b0v.z, acc1[2]));
        acc1[3] = fmaf(h1a, a0.w, fmaf(h1b, b0v.w, acc1[3]));
        acc1[4] = fmaf(h1a, a1.x, fmaf(h1b, b1v.x, acc1[4]));
        acc1[5] = fmaf(h1a, a1.y, fmaf(h1b, b1v.y, acc1[5]));
        acc1[6] = fmaf(h1a, a1.z, fmaf(h1b, b1v.z, acc1[6]));
        acc1[7] = fmaf(h1a, a1.w, fmaf(h1b, b1v.w, acc1[7]));
    }

#pragma unroll
    for (int c = 0; c < C_OUT; c++) {
#pragma unroll
        for (int o = 16; o; o >>= 1) {
            acc0[c] += __shfl_xor_sync(0xffffffffu, acc0[c], o);
            acc1[c] += __shfl_xor_sync(0xffffffffu, acc1[c], o);
        }
    }

    if (lane == 0) {
#pragma unroll
        for (int c = 0; c < C_OUT; c++) {
            g_gT[c * N_NODES + r0]     = acc0[c] + s_bias[c];
            g_gT[c * N_NODES + r0 + 1] = acc1[c] + s_bias[c];
        }
    }
}

// ---------------------------------------------------------------------------
// Main kernel: out[i,c] += sum_{j in chunk} m(nd[i,j]/nm[i,j]) * g[j,c]
//
// Grid (128 row-groups, 4 j-chunks) = 512 blocks, 3 blocks/SM (24 warps/SM).
// m(d) PWL: each block rebuilds the 64-breakpoint table; common case
// (d above max breakpoint) is fully register-resident (rcp+setp+fma, no LDS).
// 8 warps x 2 rows/warp; j-chunk of gT staged in 16KB shared; loads
// software-pipelined (8 LDG.128 in flight per warp). Partials combined with
// atomicAdd (out zeroed by g_kernel).
// ---------------------------------------------------------------------------
__global__ void __launch_bounds__(256, 3) main_kernel(
        const float* __restrict__ nd,
        const float* __restrict__ nm,
        const float* __restrict__ Wm1,
        const float* __restrict__ bm1,
        const float* __restrict__ Wm2,
        const float* __restrict__ bm2,
        float* __restrict__ out) {
    __shared__ float gTs[C_OUT * JCHUNK];   // 16KB
    __shared__ float bps[64], As[65], Bs[65];
    __shared__ float w_t[64], w_bA[64], w_bB[64], s_dA[64], s_dB[64];

    int tid = threadIdx.x;
    int jbase = blockIdx.y * JCHUNK;

    // stage gT chunk (independent of table-build syncs)
    for (int i = tid; i < C_OUT * JCHUNK; i += 256) {
        int c = i >> 9, jj = i & (JCHUNK - 1);
        gTs[i] = g_gT[c * N_NODES + jbase + jj];
    }

    // ---- build PWL table (64 threads) ----
    float da = 0.f, db = 0.f, t_local = 0.f;
    if (tid < 64) {
        float a = Wm1[tid], b = bm1[tid], c = Wm2[tid];
        float t, bA = 0.f, bB = 0.f;
        if (a != 0.f) {
            t = -b / a;
            float pa = a * c, pb = b * c;
            if (a > 0.f) { da = pa;  db = pb; }
            else         { da = -pa; db = -pb; bA = pa; bB = pb; }
        } else {
            t = __int_as_float(0x7f800000);
            if (b > 0.f) bB = b * c;
        }
        w_t[tid] = t; w_bA[tid] = bA; w_bB[tid] = bB;
        t_local = t;
    }
    __syncthreads();

    if (tid < 64) {
        int rank = 0;
        for (int h2 = 0; h2 < 64; h2++) {
            float o = w_t[h2];
            rank += (o < t_local) || (o == t_local && h2 < tid);
        }
        bps[rank] = t_local; s_dA[rank] = da; s_dB[rank] = db;
    }
    __syncthreads();

    if (tid < 32) {
        float a0 = s_dA[2 * tid], a1 = s_dA[2 * tid + 1];
        float b0 = s_dB[2 * tid], b1 = s_dB[2 * tid + 1];
        float ra = w_bA[2 * tid] + w_bA[2 * tid + 1];
        float rb = w_bB[2 * tid] + w_bB[2 * tid + 1];
#pragma unroll
        for (int o = 16; o; o >>= 1) {
            ra += __shfl_xor_sync(0xffffffffu, ra, o);
            rb += __shfl_xor_sync(0xffffffffu, rb, o);
        }
        float A0 = ra, B0 = rb + bm2[0];

        float sa = a0 + a1, sb = b0 + b1;
        float ia = sa, ib = sb;
#pragma unroll
        for (int o = 1; o < 32; o <<= 1) {
            float ua = __shfl_up_sync(0xffffffffu, ia, o);
            float ub = __shfl_up_sync(0xffffffffu, ib, o);
            if (tid >= o) { ia += ua; ib += ub; }
        }
        float ea = ia - sa, eb = ib - sb;  // exclusive prefix
        if (tid == 0) { As[0] = A0; Bs[0] = B0; }
        As[2 * tid + 1] = A0 + ea + a0;
        Bs[2 * tid + 1] = B0 + eb + b0;
        As[2 * tid + 2] = A0 + ea + a0 + a1;
        Bs[2 * tid + 2] = B0 + eb + b0 + b1;
    }
    __syncthreads();

    // register-resident fast path constants
    float top = bps[63];
    float A64 = As[64], B64 = Bs[64];

    int warp = tid >> 5, lane = tid & 31;
    int r0 = blockIdx.x * 16 + warp * 2;
    int r1 = r0 + 1;

    const float* d0 = nd + (size_t)r0 * N_NODES + jbase;
    const float* n0 = nm + (size_t)r0 * N_NODES + jbase;
    const float* d1 = nd + (size_t)r1 * N_NODES + jbase;
    const float* n1 = nm + (size_t)r1 * N_NODES + jbase;

    float acc0[C_OUT], acc1[C_OUT];
#pragma unroll
    for (int c = 0; c < C_OUT; c++) { acc0[c] = 0.f; acc1[c] = 0.f; }

    // software-pipelined over the 4 j-iterations of this chunk
    int jb = lane * 4;
    float4 dq0 = __ldcs((const float4*)(d0 + jb));
    float4 nq0 = __ldcs((const float4*)(n0 + jb));
    float4 dq1 = __ldcs((const float4*)(d1 + jb));
    float4 nq1 = __ldcs((const float4*)(n1 + jb));

#pragma unroll
    for (int it = 0; it < JCHUNK / 128; it++) {
        float4 cd0 = dq0, cn0 = nq0, cd1 = dq1, cn1 = nq1;
        int jn = jb + 128;
        if (it + 1 < JCHUNK / 128) {
            dq0 = __ldcs((const float4*)(d0 + jn));
            nq0 = __ldcs((const float4*)(n0 + jn));
            dq1 = __ldcs((const float4*)(d1 + jn));
            nq1 = __ldcs((const float4*)(n1 + jn));
        }

        float dv0[4] = {cd0.x, cd0.y, cd0.z, cd0.w};
        float nv0[4] = {cn0.x, cn0.y, cn0.z, cn0.w};
        float dv1[4] = {cd1.x, cd1.y, cd1.z, cd1.w};
        float nv1[4] = {cn1.x, cn1.y, cn1.z, cn1.w};

        float m0[4], m1[4];
#pragma unroll
        for (int t = 0; t < 4; t++) {
            float d = __fdividef(dv0[t], nv0[t]);
            if (top < d) {                     // fast path: no LDS at all
                m0[t] = fmaf(A64, d, B64);
            } else {
                int k = 0;
#pragma unroll
                for (int s = 32; s >= 1; s >>= 1)
                    if (bps[k + s - 1] < d) k += s;
                m0[t] = fmaf(As[k], d, Bs[k]);
            }
            float e = __fdividef(dv1[t], nv1[t]);
            if (top < e) {
                m1[t] = fmaf(A64, e, B64);
            } else {
                int k2 = 0;
#pragma unroll
                for (int s = 32; s >= 1; s >>= 1)
                    if (bps[k2 + s - 1] < e) k2 += s;
                m1[t] = fmaf(As[k2], e, Bs[k2]);
            }
        }

#pragma unroll
        for (int c = 0; c < C_OUT; c++) {
            float4 gv = *(const float4*)(gTs + c * JCHUNK + jb);
            acc0[c] = fmaf(m0[0], gv.x, acc0[c]);
            acc0[c] = fmaf(m0[1], gv.y, acc0[c]);
            acc0[c] = fmaf(m0[2], gv.z, acc0[c]);
            acc0[c] = fmaf(m0[3], gv.w, acc0[c]);
            acc1[c] = fmaf(m1[0], gv.x, acc1[c]);
            acc1[c] = fmaf(m1[1], gv.y, acc1[c]);
            acc1[c] = fmaf(m1[2], gv.z, acc1[c]);
            acc1[c] = fmaf(m1[3], gv.w, acc1[c]);
        }
        jb = jn;
    }

#pragma unroll
    for (int c = 0; c < C_OUT; c++) {
#pragma unroll
        for (int o = 16; o; o >>= 1) {
            acc0[c] += __shfl_xor_sync(0xffffffffu, acc0[c], o);
            acc1[c] += __shfl_xor_sync(0xffffffffu, acc1[c], o);
        }
    }

    if (lane == 0) {
#pragma unroll
        for (int c = 0; c < C_OUT; c++) {
            atomicAdd(&out[r0 * C_OUT + c], acc0[c]);
            atomicAdd(&out[r1 * C_OUT + c], acc1[c]);
        }
    }
}

// ---------------------------------------------------------------------------
extern "C" void kernel_launch(void* const* d_in, const int* in_sizes, int n_in,
                              void* d_out, int out_size) {
    const float* x   = (const float*)d_in[0];
    const float* nd  = (const float*)d_in[1];
    const float* nm  = (const float*)d_in[2];
    const float* W1  = (const float*)d_in[3];
    const float* b1  = (const float*)d_in[4];
    const float* W2  = (const float*)d_in[5];
    const float* b2  = (const float*)d_in[6];
    const float* Wm1 = (const float*)d_in[7];
    const float* bm1 = (const float*)d_in[8];
    const float* Wm2 = (const float*)d_in[9];
    const float* bm2 = (const float*)d_in[10];
    float* out = (float*)d_out;

    g_kernel<<<N_NODES / 16, 256>>>(x, W1, b1, W2, b2, out);

    dim3 grid(N_NODES / 16, NSPLIT);
    main_kernel<<<grid, 256>>>(nd, nm, Wm1, bm1, Wm2, bm2, out);
}

// round 6
// speedup vs baseline: 1.5641x; 1.2163x over previous
#include <cuda_runtime.h>
#include <cstdint>

#define N_NODES 2048
#define F_FEAT  64
#define H_HID   64
#define C_OUT   8
#define JCHUNK  512
#define NSPLIT  (N_NODES / JCHUNK)   // 4 j-chunks
#define FSPLIT  4
#define FPER    (F_FEAT / FSPLIT)    // 16 features per split

// partial g, per f-split: [s][c][j]  (pure writes -> replay-safe)
__device__ float g_part[FSPLIT * C_OUT * N_NODES];
// PWL table for m(d), built once by g_kernel block (0,0) warp 0
__device__ float g_bpG[64];
__device__ float g_AG[65];
__device__ float g_BG[65];

// fma-pipe reciprocal: magic init + 2 Newton iterations (rel err ~6e-6)
__device__ __forceinline__ float frcp_nr(float y) {
    float r = __int_as_float(0x7EF311C3 - __float_as_int(y));
    r = r * fmaf(-y, r, 2.0f);
    r = r * fmaf(-y, r, 2.0f);
    return r;
}

// ---------------------------------------------------------------------------
// g kernel: grid (64 rowgroups, 4 f-splits) x 256 threads.
// Each warp: 4 rows x 16 features -> weight L1 traffic amortized 4x.
// g_part[s][c][j] = sum_{f in split s} sum_h relu(x*W1+b1)*W2 + sum_{f in s} b2
// Block (0,0) warp 0 additionally builds the PWL table for m(d).
// fs==0 blocks zero `out` (main accumulates atomically; replay-safe).
// ---------------------------------------------------------------------------
__global__ void __launch_bounds__(256) g_kernel(
        const float* __restrict__ x,
        const float* __restrict__ W1,
        const float* __restrict__ b1,
        const float* __restrict__ W2,
        const float* __restrict__ b2,
        const float* __restrict__ Wm1,
        const float* __restrict__ bm1,
        const float* __restrict__ Wm2,
        const float* __restrict__ bm2,
        float* __restrict__ out) {
    __shared__ float s_bias[C_OUT];
    __shared__ float w_t[64], s_bp[64], s_dA[64], s_dB[64];

    int tid  = threadIdx.x;
    int lane = tid & 31;
    int warp = tid >> 5;
    int by   = blockIdx.x;
    int fs   = blockIdx.y;
    int fbase = fs * FPER;

    // zero out (poisoned by harness; must be re-zeroed each graph replay)
    if (fs == 0)
        out[by * 256 + tid] = 0.f;

    // split-local bias: s_bias[c] = sum_{f in split} b2[f,c]
    if (tid < C_OUT) {
        float s = 0.f;
#pragma unroll
        for (int fi = 0; fi < FPER; fi++)
            s += b2[(fbase + fi) * C_OUT + tid];
        s_bias[tid] = s;
    }

    // ---- PWL table build (block (0,0), warp 0 only) ----
    if (by == 0 && fs == 0 && warp == 0) {
        // 2 hidden units per lane
        float t[2], da[2], db[2], bA[2], bB[2];
#pragma unroll
        for (int e = 0; e < 2; e++) {
            int h = lane + e * 32;
            float a = Wm1[h], b = bm1[h], c = Wm2[h];
            float tt, vda = 0.f, vdb = 0.f, vbA = 0.f, vbB = 0.f;
            if (a != 0.f) {
                tt = -b / a;
                float pa = a * c, pb = b * c;
                if (a > 0.f) { vda = pa;  vdb = pb; }
                else         { vda = -pa; vdb = -pb; vbA = pa; vbB = pb; }
            } else {
                tt = __int_as_float(0x7f800000);
                if (b > 0.f) vbB = b * c;
            }
            t[e] = tt; da[e] = vda; db[e] = vdb; bA[e] = vbA; bB[e] = vbB;
        }
        w_t[lane] = t[0]; w_t[lane + 32] = t[1];
        __syncwarp();

        int rk[2] = {0, 0};
        for (int k = 0; k < 64; k++) {
            float o = w_t[k];
            rk[0] += (o < t[0]) || (o == t[0] && k < lane);
            rk[1] += (o < t[1]) || (o == t[1] && k < lane + 32);
        }
        s_bp[rk[0]] = t[0]; s_dA[rk[0]] = da[0]; s_dB[rk[0]] = db[0];
        s_bp[rk[1]] = t[1]; s_dA[rk[1]] = da[1]; s_dB[rk[1]] = db[1];
        __syncwarp();

        // base-state reduce
        float ra = bA[0] + bA[1], rb = bB[0] + bB[1];
#pragma unroll
        for (int o = 16; o; o >>= 1) {
            ra += __shfl_xor_sync(0xffffffffu, ra, o);
            rb += __shfl_xor_sync(0xffffffffu, rb, o);
        }
        float A0 = ra, B0 = rb + bm2[0];

        // inclusive scan of sorted deltas, 2 per lane
        float a0 = s_dA[2 * lane], a1 = s_dA[2 * lane + 1];
        float b0 = s_dB[2 * lane], b1v = s_dB[2 * lane + 1];
        float sa = a0 + a1, sb = b0 + b1v;
        float ia = sa, ib = sb;
#pragma unroll
        for (int o = 1; o < 32; o <<= 1) {
            float ua = __shfl_up_sync(0xffffffffu, ia, o);
            float ub = __shfl_up_sync(0xffffffffu, ib, o);
            if (lane >= o) { ia += ua; ib += ub; }
        }
        float ea = ia - sa, eb = ib - sb;   // exclusive prefix
        if (lane == 0) { g_AG[0] = A0; g_BG[0] = B0; }
        g_AG[2 * lane + 1] = A0 + ea + a0;
        g_BG[2 * lane + 1] = B0 + eb + b0;
        g_AG[2 * lane + 2] = A0 + ea + a0 + a1;
        g_BG[2 * lane + 2] = B0 + eb + b0 + b1v;
        g_bpG[2 * lane]     = s_bp[2 * lane];
        g_bpG[2 * lane + 1] = s_bp[2 * lane + 1];
    }

    // ---- per-feature NAM accumulation ----
    int r0 = by * 32 + warp * 4;     // 4 rows per warp
    int h0 = lane, h1 = lane + 32;

    float xr[4];
#pragma unroll
    for (int r = 0; r < 4; r++)
        xr[r] = x[(r0 + r) * F_FEAT + fbase + (lane & 15)];

    float acc[4][C_OUT];
#pragma unroll
    for (int r = 0; r < 4; r++)
#pragma unroll
        for (int c = 0; c < C_OUT; c++) acc[r][c] = 0.f;

#pragma unroll 4
    for (int fi = 0; fi < FPER; fi++) {
        int f = fbase + fi;
        float w1a = W1[f * 64 + h0], w1b = W1[f * 64 + h1];
        float c1a = b1[f * 64 + h0], c1b = b1[f * 64 + h1];
        const float4* wa = (const float4*)(W2 + (size_t)(f * 64 + h0) * 8);
        const float4* wb = (const float4*)(W2 + (size_t)(f * 64 + h1) * 8);
        float4 a0 = wa[0], a1 = wa[1];
        float4 b0v = wb[0], b1w = wb[1];

#pragma unroll
        for (int r = 0; r < 4; r++) {
            float xv = __shfl_sync(0xffffffffu, xr[r], fi);
            float ha = fmaxf(fmaf(xv, w1a, c1a), 0.f);
            float hb = fmaxf(fmaf(xv, w1b, c1b), 0.f);

            acc[r][0] = fmaf(ha, a0.x, fmaf(hb, b0v.x, acc[r][0]));
            acc[r][1] = fmaf(ha, a0.y, fmaf(hb, b0v.y, acc[r][1]));
            acc[r][2] = fmaf(ha, a0.z, fmaf(hb, b0v.z, acc[r][2]));
            acc[r][3] = fmaf(ha, a0.w, fmaf(hb, b0v.w, acc[r][3]));
            acc[r][4] = fmaf(ha, a1.x, fmaf(hb, b1w.x, acc[r][4]));
            acc[r][5] = fmaf(ha, a1.y, fmaf(hb, b1w.y, acc[r][5]));
            acc[r][6] = fmaf(ha, a1.z, fmaf(hb, b1w.z, acc[r][6]));
            acc[r][7] = fmaf(ha, a1.w, fmaf(hb, b1w.w, acc[r][7]));
        }
    }

#pragma unroll
    for (int r = 0; r < 4; r++)
#pragma unroll
        for (int c = 0; c < C_OUT; c++)
#pragma unroll
            for (int o = 16; o; o >>= 1)
                acc[r][c] += __shfl_xor_sync(0xffffffffu, acc[r][c], o);

    __syncthreads();   // s_bias ready
    if (lane == 0) {
#pragma unroll
        for (int r = 0; r < 4; r++)
#pragma unroll
            for (int c = 0; c < C_OUT; c++)
                g_part[(fs * C_OUT + c) * N_NODES + r0 + r] = acc[r][c] + s_bias[c];
    }
}

// ---------------------------------------------------------------------------
// Main kernel: out[i,c] += sum_{j in chunk} m(nd[i,j]/nm[i,j]) * g[j,c]
// Grid (128 rowgroups x 4 j-chunks) = 512 blocks, 4 blocks/SM (32 warps/SM,
// single wave). Division done on the fma pipe (magic+Newton) -- no MUFU.
// PWL table loaded from globals (built once in g_kernel). gT chunk staged in
// 16KB shared as the sum of the 4 f-split partials (L2-resident).
// ---------------------------------------------------------------------------
__global__ void __launch_bounds__(256, 4) main_kernel(
        const float* __restrict__ nd,
        const float* __restrict__ nm,
        float* __restrict__ out) {
    __shared__ float gTs[C_OUT * JCHUNK];   // 16KB
    __shared__ float bps[64], As[65], Bs[65];

    int tid = threadIdx.x;
    int jbase = blockIdx.y * JCHUNK;

    if (tid < 64) bps[tid] = g_bpG[tid];
    else if (tid < 129) As[tid - 64] = g_AG[tid - 64];
    else if (tid < 194) Bs[tid - 129] = g_BG[tid - 129];

    for (int i = tid; i < C_OUT * JCHUNK; i += 256) {
        int c = i >> 9, jj = i & (JCHUNK - 1);
        int gj = c * N_NODES + jbase + jj;
        gTs[i] = g_part[gj]
               + g_part[1 * C_OUT * N_NODES + gj]
               + g_part[2 * C_OUT * N_NODES + gj]
               + g_part[3 * C_OUT * N_NODES + gj];
    }
    __syncthreads();

    float top = bps[63];
    float A64 = As[64], B64 = Bs[64];

    int warp = tid >> 5, lane = tid & 31;
    int r0 = blockIdx.x * 16 + warp * 2;
    int r1 = r0 + 1;

    const float* d0 = nd + (size_t)r0 * N_NODES + jbase;
    const float* n0 = nm + (size_t)r0 * N_NODES + jbase;
    const float* d1 = nd + (size_t)r1 * N_NODES + jbase;
    const float* n1 = nm + (size_t)r1 * N_NODES + jbase;

    float acc0[C_OUT], acc1[C_OUT];
#pragma unroll
    for (int c = 0; c < C_OUT; c++) { acc0[c] = 0.f; acc1[c] = 0.f; }

    int jb = lane * 4;
    float4 dq0 = __ldcs((const float4*)(d0 + jb));
    float4 nq0 = __ldcs((const float4*)(n0 + jb));
    float4 dq1 = __ldcs((const float4*)(d1 + jb));
    float4 nq1 = __ldcs((const float4*)(n1 + jb));

#pragma unroll
    for (int it = 0; it < JCHUNK / 128; it++) {
        float4 cd0 = dq0, cn0 = nq0, cd1 = dq1, cn1 = nq1;
        int jn = jb + 128;
        if (it + 1 < JCHUNK / 128) {
            dq0 = __ldcs((const float4*)(d0 + jn));
            nq0 = __ldcs((const float4*)(n0 + jn));
            dq1 = __ldcs((const float4*)(d1 + jn));
            nq1 = __ldcs((const float4*)(n1 + jn));
        }

        float dv0[4] = {cd0.x, cd0.y, cd0.z, cd0.w};
        float nv0[4] = {cn0.x, cn0.y, cn0.z, cn0.w};
        float dv1[4] = {cd1.x, cd1.y, cd1.z, cd1.w};
        float nv1[4] = {cn1.x, cn1.y, cn1.z, cn1.w};

        float m0[4], m1[4];
#pragma unroll
        for (int t = 0; t < 4; t++) {
            float d = dv0[t] * frcp_nr(nv0[t]);
            if (top < d) {                     // fast path: register-only
                m0[t] = fmaf(A64, d, B64);
            } else {
                int k = 0;
#pragma unroll
                for (int s = 32; s >= 1; s >>= 1)
                    if (bps[k + s - 1] < d) k += s;
                m0[t] = fmaf(As[k], d, Bs[k]);
            }
            float e = dv1[t] * frcp_nr(nv1[t]);
            if (top < e) {
                m1[t] = fmaf(A64, e, B64);
            } else {
                int k2 = 0;
#pragma unroll
                for (int s = 32; s >= 1; s >>= 1)
                    if (bps[k2 + s - 1] < e) k2 += s;
                m1[t] = fmaf(As[k2], e, Bs[k2]);
            }
        }

#pragma unroll
        for (int c = 0; c < C_OUT; c++) {
            float4 gv = *(const float4*)(gTs + c * JCHUNK + jb);
            acc0[c] = fmaf(m0[0], gv.x, acc0[c]);
            acc0[c] = fmaf(m0[1], gv.y, acc0[c]);
            acc0[c] = fmaf(m0[2], gv.z, acc0[c]);
            acc0[c] = fmaf(m0[3], gv.w, acc0[c]);
            acc1[c] = fmaf(m1[0], gv.x, acc1[c]);
            acc1[c] = fmaf(m1[1], gv.y, acc1[c]);
            acc1[c] = fmaf(m1[2], gv.z, acc1[c]);
            acc1[c] = fmaf(m1[3], gv.w, acc1[c]);
        }
        jb = jn;
    }

#pragma unroll
    for (int c = 0; c < C_OUT; c++) {
#pragma unroll
        for (int o = 16; o; o >>= 1) {
            acc0[c] += __shfl_xor_sync(0xffffffffu, acc0[c], o);
            acc1[c] += __shfl_xor_sync(0xffffffffu, acc1[c], o);
        }
    }

    if (lane == 0) {
#pragma unroll
        for (int c = 0; c < C_OUT; c++) {
            atomicAdd(&out[r0 * C_OUT + c], acc0[c]);
            atomicAdd(&out[r1 * C_OUT + c], acc1[c]);
        }
    }
}

// ---------------------------------------------------------------------------
extern "C" void kernel_launch(void* const* d_in, const int* in_sizes, int n_in,
                              void* d_out, int out_size) {
    const float* x   = (const float*)d_in[0];
    const float* nd  = (const float*)d_in[1];
    const float* nm  = (const float*)d_in[2];
    const float* W1  = (const float*)d_in[3];
    const float* b1  = (const float*)d_in[4];
    const float* W2  = (const float*)d_in[5];
    const float* b2  = (const float*)d_in[6];
    const float* Wm1 = (const float*)d_in[7];
    const float* bm1 = (const float*)d_in[8];
    const float* Wm2 = (const float*)d_in[9];
    const float* bm2 = (const float*)d_in[10];
    float* out = (float*)d_out;

    dim3 ggrid(N_NODES / 32, FSPLIT);
    g_kernel<<<ggrid, 256>>>(x, W1, b1, W2, b2, Wm1, bm1, Wm2, bm2, out);

    dim3 mgrid(N_NODES / 16, NSPLIT);
    main_kernel<<<mgrid, 256>>>(nd, nm, out);
}

// round 8
// speedup vs baseline: 2.4010x; 1.5351x over previous
#include <cuda_runtime.h>
#include <cstdint>

#define N_NODES 2048
#define F_FEAT  64
#define H_HID   64
#define C_OUT   8
#define JCHUNK  512
#define NSPLIT  (N_NODES / JCHUNK)   // 4 j-chunks
#define FSPLIT  2
#define FPER    (F_FEAT / FSPLIT)    // 32 features per split

// partial g, per f-half: [s][c][j]  (pure writes -> replay-safe)
__device__ __align__(16) float g_part[FSPLIT * C_OUT * N_NODES];
// PWL table for m(d), built once by g_kernel block (0,0) warp 0
__device__ float g_bpG[64];
__device__ float g_AG[65];
__device__ float g_BG[65];

// fma-pipe reciprocal: magic init + 2 Newton iterations (rel err ~6e-6)
__device__ __forceinline__ float frcp_nr(float y) {
    float r = __int_as_float(0x7EF311C3 - __float_as_int(y));
    r = r * fmaf(-y, r, 2.0f);
    r = r * fmaf(-y, r, 2.0f);
    return r;
}

// ---------------------------------------------------------------------------
// g kernel: grid (64 rowgroups, 2 f-halves) x 256 threads (8 warps).
// Each warp: 4 rows x 32 features (weight L1 traffic amortized 4x).
// g_part[s][c][j] = sum_{f in half s} sum_h relu(x*W1+b1)*W2 + sum_{f} b2
// Block (0,0) warp 0 additionally builds the PWL table for m(d).
// fs==0 blocks zero `out` (main accumulates atomically; replay-safe).
// ---------------------------------------------------------------------------
__global__ void __launch_bounds__(256) g_kernel(
        const float* __restrict__ x,
        const float* __restrict__ W1,
        const float* __restrict__ b1,
        const float* __restrict__ W2,
        const float* __restrict__ b2,
        const float* __restrict__ Wm1,
        const float* __restrict__ bm1,
        const float* __restrict__ Wm2,
        const float* __restrict__ bm2,
        float* __restrict__ out) {
    __shared__ float s_bias[C_OUT];
    __shared__ float w_t[64], s_bp[64], s_dA[64], s_dB[64];

    int tid  = threadIdx.x;
    int lane = tid & 31;
    int warp = tid >> 5;
    int by   = blockIdx.x;
    int fs   = blockIdx.y;
    int fbase = fs * FPER;

    // zero out (poisoned by harness; re-zeroed every graph replay)
    if (fs == 0)
        out[by * 256 + tid] = 0.f;   // 64 blocks x 256 = 16384 = N*C

    // half-local bias: s_bias[c] = sum_{f in half} b2[f,c]
    if (tid < C_OUT) {
        float s = 0.f;
#pragma unroll
        for (int fi = 0; fi < FPER; fi++)
            s += b2[(fbase + fi) * C_OUT + tid];
        s_bias[tid] = s;
    }

    // ---- PWL table build (block (0,0), warp 0 only) ----
    if (by == 0 && fs == 0 && warp == 0) {
        float t[2], da[2], db[2], bA[2], bB[2];
#pragma unroll
        for (int e = 0; e < 2; e++) {
            int h = lane + e * 32;
            float a = Wm1[h], b = bm1[h], c = Wm2[h];
            float tt, vda = 0.f, vdb = 0.f, vbA = 0.f, vbB = 0.f;
            if (a != 0.f) {
                tt = -b / a;
                float pa = a * c, pb = b * c;
                if (a > 0.f) { vda = pa;  vdb = pb; }
                else         { vda = -pa; vdb = -pb; vbA = pa; vbB = pb; }
            } else {
                tt = __int_as_float(0x7f800000);
                if (b > 0.f) vbB = b * c;
            }
            t[e] = tt; da[e] = vda; db[e] = vdb; bA[e] = vbA; bB[e] = vbB;
        }
        w_t[lane] = t[0]; w_t[lane + 32] = t[1];
        __syncwarp();

        int rk[2] = {0, 0};
        for (int k = 0; k < 64; k++) {
            float o = w_t[k];
            rk[0] += (o < t[0]) || (o == t[0] && k < lane);
            rk[1] += (o < t[1]) || (o == t[1] && k < lane + 32);
        }
        s_bp[rk[0]] = t[0]; s_dA[rk[0]] = da[0]; s_dB[rk[0]] = db[0];
        s_bp[rk[1]] = t[1]; s_dA[rk[1]] = da[1]; s_dB[rk[1]] = db[1];
        __syncwarp();

        float ra = bA[0] + bA[1], rb = bB[0] + bB[1];
#pragma unroll
        for (int o = 16; o; o >>= 1) {
            ra += __shfl_xor_sync(0xffffffffu, ra, o);
            rb += __shfl_xor_sync(0xffffffffu, rb, o);
        }
        float A0 = ra, B0 = rb + bm2[0];

        float a0 = s_dA[2 * lane], a1 = s_dA[2 * lane + 1];
        float b0 = s_dB[2 * lane], b1v = s_dB[2 * lane + 1];
        float sa = a0 + a1, sb = b0 + b1v;
        float ia = sa, ib = sb;
#pragma unroll
        for (int o = 1; o < 32; o <<= 1) {
            float ua = __shfl_up_sync(0xffffffffu, ia, o);
            float ub = __shfl_up_sync(0xffffffffu, ib, o);
            if (lane >= o) { ia += ua; ib += ub; }
        }
        float ea = ia - sa, eb = ib - sb;   // exclusive prefix
        if (lane == 0) { g_AG[0] = A0; g_BG[0] = B0; }
        g_AG[2 * lane + 1] = A0 + ea + a0;
        g_BG[2 * lane + 1] = B0 + eb + b0;
        g_AG[2 * lane + 2] = A0 + ea + a0 + a1;
        g_BG[2 * lane + 2] = B0 + eb + b0 + b1v;
        g_bpG[2 * lane]     = s_bp[2 * lane];
        g_bpG[2 * lane + 1] = s_bp[2 * lane + 1];
    }

    // ---- per-feature NAM accumulation: 4 rows x 32 features per warp ----
    int r0 = by * 32 + warp * 4;
    int h0 = lane, h1 = lane + 32;

    float xr[4];
#pragma unroll
    for (int r = 0; r < 4; r++)
        xr[r] = x[(r0 + r) * F_FEAT + fbase + lane];

    float acc[4][C_OUT];
#pragma unroll
    for (int r = 0; r < 4; r++)
#pragma unroll
        for (int c = 0; c < C_OUT; c++) acc[r][c] = 0.f;

#pragma unroll 4
    for (int fi = 0; fi < FPER; fi++) {
        int f = fbase + fi;
        float w1a = W1[f * 64 + h0], w1b = W1[f * 64 + h1];
        float c1a = b1[f * 64 + h0], c1b = b1[f * 64 + h1];
        const float4* wa = (const float4*)(W2 + (size_t)(f * 64 + h0) * 8);
        const float4* wb = (const float4*)(W2 + (size_t)(f * 64 + h1) * 8);
        float4 a0 = wa[0], a1 = wa[1];
        float4 b0v = wb[0], b1w = wb[1];

#pragma unroll
        for (int r = 0; r < 4; r++) {
            float xv = __shfl_sync(0xffffffffu, xr[r], fi);
            float ha = fmaxf(fmaf(xv, w1a, c1a), 0.f);
            float hb = fmaxf(fmaf(xv, w1b, c1b), 0.f);

            acc[r][0] = fmaf(ha, a0.x, fmaf(hb, b0v.x, acc[r][0]));
            acc[r][1] = fmaf(ha, a0.y, fmaf(hb, b0v.y, acc[r][1]));
            acc[r][2] = fmaf(ha, a0.z, fmaf(hb, b0v.z, acc[r][2]));
            acc[r][3] = fmaf(ha, a0.w, fmaf(hb, b0v.w, acc[r][3]));
            acc[r][4] = fmaf(ha, a1.x, fmaf(hb, b1w.x, acc[r][4]));
            acc[r][5] = fmaf(ha, a1.y, fmaf(hb, b1w.y, acc[r][5]));
            acc[r][6] = fmaf(ha, a1.z, fmaf(hb, b1w.z, acc[r][6]));
            acc[r][7] = fmaf(ha, a1.w, fmaf(hb, b1w.w, acc[r][7]));
        }
    }

#pragma unroll
    for (int r = 0; r < 4; r++)
#pragma unroll
        for (int c = 0; c < C_OUT; c++)
#pragma unroll
            for (int o = 16; o; o >>= 1)
                acc[r][c] += __shfl_xor_sync(0xffffffffu, acc[r][c], o);

    __syncthreads();   // s_bias ready
    if (lane == 0) {
#pragma unroll
        for (int r = 0; r < 4; r++)
#pragma unroll
            for (int c = 0; c < C_OUT; c++)
                g_part[(fs * C_OUT + c) * N_NODES + r0 + r] = acc[r][c] + s_bias[c];
    }
}

// ---------------------------------------------------------------------------
// Main kernel: out[i,c] += sum_{j in chunk} m(nd[i,j]/nm[i,j]) * g[j,c]
// Grid (128 rowgroups x 4 j-chunks) = 512 blocks, 4/SM (32 warps/SM).
// Reciprocal on the fma pipe. Segment select: ONE warp-uniform vote per
// iteration (min of 8 d's vs max breakpoint) -> fast path is branch-free
// straight-line FMA; rare slow path searches the L1-resident global table.
// gT chunk staged in 16KB shared via float4 (2 partials summed).
// ---------------------------------------------------------------------------
__global__ void __launch_bounds__(256, 4) main_kernel(
        const float* __restrict__ nd,
        const float* __restrict__ nm,
        float* __restrict__ out) {
    __shared__ float gTs[C_OUT * JCHUNK];   // 16KB

    int tid = threadIdx.x;
    int jbase = blockIdx.y * JCHUNK;

    // stage gT chunk: float4 loads, sum of the 2 f-half partials
    {
        const float4* g4 = (const float4*)g_part;
        const int half4 = (C_OUT * N_NODES) >> 2;
#pragma unroll
        for (int i = tid; i < (C_OUT * JCHUNK) >> 2; i += 256) {
            int c = i >> 7, j4 = i & 127;            // 128 float4 per c-row
            int off = ((c * N_NODES + jbase) >> 2) + j4;
            float4 a = g4[off];
            float4 b = g4[half4 + off];
            float4 s = make_float4(a.x + b.x, a.y + b.y, a.z + b.z, a.w + b.w);
            ((float4*)gTs)[i] = s;
        }
    }

    float top = __ldg(&g_bpG[63]);
    float A64 = __ldg(&g_AG[64]);
    float B64 = __ldg(&g_BG[64]);
    __syncthreads();

    int warp = tid >> 5, lane = tid & 31;
    int r0 = blockIdx.x * 16 + warp * 2;
    int r1 = r0 + 1;

    const float* d0p = nd + (size_t)r0 * N_NODES + jbase;
    const float* n0p = nm + (size_t)r0 * N_NODES + jbase;
    const float* d1p = nd + (size_t)r1 * N_NODES + jbase;
    const float* n1p = nm + (size_t)r1 * N_NODES + jbase;

    float acc0[C_OUT], acc1[C_OUT];
#pragma unroll
    for (int c = 0; c < C_OUT; c++) { acc0[c] = 0.f; acc1[c] = 0.f; }

    int jb = lane * 4;
    float4 dq0 = __ldcs((const float4*)(d0p + jb));
    float4 nq0 = __ldcs((const float4*)(n0p + jb));
    float4 dq1 = __ldcs((const float4*)(d1p + jb));
    float4 nq1 = __ldcs((const float4*)(n1p + jb));

#pragma unroll
    for (int it = 0; it < JCHUNK / 128; it++) {
        float4 cd0 = dq0, cn0 = nq0, cd1 = dq1, cn1 = nq1;
        int jn = jb + 128;
        if (it + 1 < JCHUNK / 128) {
            dq0 = __ldcs((const float4*)(d0p + jn));
            nq0 = __ldcs((const float4*)(n0p + jn));
            dq1 = __ldcs((const float4*)(d1p + jn));
            nq1 = __ldcs((const float4*)(n1p + jn));
        }

        float dv[8], m[8];
        dv[0] = cd0.x * frcp_nr(cn0.x);
        dv[1] = cd0.y * frcp_nr(cn0.y);
        dv[2] = cd0.z * frcp_nr(cn0.z);
        dv[3] = cd0.w * frcp_nr(cn0.w);
        dv[4] = cd1.x * frcp_nr(cn1.x);
        dv[5] = cd1.y * frcp_nr(cn1.y);
        dv[6] = cd1.z * frcp_nr(cn1.z);
        dv[7] = cd1.w * frcp_nr(cn1.w);

        float mn = fminf(fminf(fminf(dv[0], dv[1]), fminf(dv[2], dv[3])),
                         fminf(fminf(dv[4], dv[5]), fminf(dv[6], dv[7])));

        if (__all_sync(0xffffffffu, mn > top)) {
            // fast path: all 8 pairs in the top segment -- pure FMA
#pragma unroll
            for (int t = 0; t < 8; t++)
                m[t] = fmaf(A64, dv[t], B64);
        } else {
            // rare path: binary search in the L1-resident global table
#pragma unroll
            for (int t = 0; t < 8; t++) {
                float d = dv[t];
                int k = 0;
#pragma unroll
                for (int s = 32; s >= 1; s >>= 1)
                    if (__ldg(&g_bpG[k + s - 1]) < d) k += s;
                m[t] = fmaf(__ldg(&g_AG[k]), d, __ldg(&g_BG[k]));
            }
        }

#pragma unroll
        for (int c = 0; c < C_OUT; c++) {
            float4 gv = *(const float4*)(gTs + c * JCHUNK + jb);
            acc0[c] = fmaf(m[0], gv.x, acc0[c]);
            acc0[c] = fmaf(m[1], gv.y, acc0[c]);
            acc0[c] = fmaf(m[2], gv.z, acc0[c]);
            acc0[c] = fmaf(m[3], gv.w, acc0[c]);
            acc1[c] = fmaf(m[4], gv.x, acc1[c]);
            acc1[c] = fmaf(m[5], gv.y, acc1[c]);
            acc1[c] = fmaf(m[6], gv.z, acc1[c]);
            acc1[c] = fmaf(m[7], gv.w, acc1[c]);
        }
        jb = jn;
    }

#pragma unroll
    for (int c = 0; c < C_OUT; c++) {
#pragma unroll
        for (int o = 16; o; o >>= 1) {
            acc0[c] += __shfl_xor_sync(0xffffffffu, acc0[c], o);
            acc1[c] += __shfl_xor_sync(0xffffffffu, acc1[c], o);
        }
    }

    if (lane == 0) {
#pragma unroll
        for (int c = 0; c < C_OUT; c++) {
            atomicAdd(&out[r0 * C_OUT + c], acc0[c]);
            atomicAdd(&out[r1 * C_OUT + c], acc1[c]);
        }
    }
}

// ---------------------------------------------------------------------------
extern "C" void kernel_launch(void* const* d_in, const int* in_sizes, int n_in,
                              void* d_out, int out_size) {
    const float* x   = (const float*)d_in[0];
    const float* nd  = (const float*)d_in[1];
    const float* nm  = (const float*)d_in[2];
    const float* W1  = (const float*)d_in[3];
    const float* b1  = (const float*)d_in[4];
    const float* W2  = (const float*)d_in[5];
    const float* b2  = (const float*)d_in[6];
    const float* Wm1 = (const float*)d_in[7];
    const float* bm1 = (const float*)d_in[8];
    const float* Wm2 = (const float*)d_in[9];
    const float* bm2 = (const float*)d_in[10];
    float* out = (float*)d_out;

    dim3 ggrid(N_NODES / 32, FSPLIT);
    g_kernel<<<ggrid, 256>>>(x, W1, b1, W2, b2, Wm1, bm1, Wm2, bm2, out);

    dim3 mgrid(N_NODES / 16, NSPLIT);
    main_kernel<<<mgrid, 256>>>(nd, nm, out);
}